// round 12
// baseline (speedup 1.0000x reference)
#include <cuda_runtime.h>
#include <cuda_fp16.h>
#include <cstdint>

#define N_NODES 8192
#define D       512
#define CAP     256

// ---- scratch (device globals) ----
__device__ int    g_csr[N_NODES * CAP];
__device__ int    g_cnt[N_NODES];
__device__ float  g_dis[N_NODES];
__device__ uint4  g_ys[N_NODES * D / 8];   // ys = dis[m] * (x @ W^T)[m], fp16 (8 halves/uint4)

__device__ __forceinline__ uint32_t smem_u32(const void* p) {
    uint32_t a;
    asm("{ .reg .u64 t; cvta.to.shared.u64 t, %1; cvt.u32.u64 %0, t; }" : "=r"(a) : "l"(p));
    return a;
}

// =====================================================================
// fp16 mma helper (m16n8k16, f32 accumulate) — legacy mma.sync path;
// tcgen05 is unavailable at this bench's compile target (sm_100 virtual).
// =====================================================================
__device__ __forceinline__ void mma_fp16(float* c, const uint32_t* a, const uint32_t* b) {
    asm volatile(
        "mma.sync.aligned.m16n8k16.row.col.f32.f16.f16.f32 "
        "{%0,%1,%2,%3}, {%4,%5,%6,%7}, {%8,%9}, {%0,%1,%2,%3};\n"
        : "+f"(c[0]), "+f"(c[1]), "+f"(c[2]), "+f"(c[3])
        : "r"(a[0]), "r"(a[1]), "r"(a[2]), "r"(a[3]), "r"(b[0]), "r"(b[1]));
}

// =====================================================================
// Kernel 1: CSR build — one block per row of dense A.
// cp.async (LDGSTS) streams the row into smem: in-flight bytes don't
// occupy destination registers, so MLP is deep AND occupancy stays high
// (R11: register prefetch gave MLP=8 but occ 67.9% -> DRAM 74.7%).
// =====================================================================
__global__ __launch_bounds__(256) void build_csr_kernel(const float* __restrict__ A) {
    __shared__ float4 s_buf[2048];                     // 32 KB row staging
    __shared__ int s_cnt;
    const int tid = threadIdx.x;
    const int row = blockIdx.x;
    if (tid == 0) s_cnt = 0;

    const float4* Arow = reinterpret_cast<const float4*>(A + (size_t)row * N_NODES);
    const uint32_t sbase = smem_u32(s_buf);

    // 8 x 16B cp.async per thread; dst interleaved [i*256 + tid] so the
    // readback LDS.128 is lane-contiguous (conflict-free).
    #pragma unroll
    for (int i = 0; i < 8; i++) {
        uint32_t dst = sbase + (uint32_t)(i * 256 + tid) * 16u;
        asm volatile("cp.async.cg.shared.global [%0], [%1], 16;"
                     :: "r"(dst), "l"(Arow + tid + i * 256) : "memory");
    }
    asm volatile("cp.async.commit_group;" ::: "memory");
    asm volatile("cp.async.wait_group 0;" ::: "memory");
    __syncthreads();                                   // s_cnt init + all slices landed

    int* csr_row = g_csr + row * CAP;
    #pragma unroll
    for (int i = 0; i < 8; i++) {
        float4 f = s_buf[i * 256 + tid];
        int base = (tid + i * 256) * 4;
        if (f.x != 0.0f) { int s = atomicAdd(&s_cnt, 1); if (s < CAP) csr_row[s] = base;     }
        if (f.y != 0.0f) { int s = atomicAdd(&s_cnt, 1); if (s < CAP) csr_row[s] = base + 1; }
        if (f.z != 0.0f) { int s = atomicAdd(&s_cnt, 1); if (s < CAP) csr_row[s] = base + 2; }
        if (f.w != 0.0f) { int s = atomicAdd(&s_cnt, 1); if (s < CAP) csr_row[s] = base + 3; }
    }
    __syncthreads();
    if (tid == 0) {
        int c = s_cnt;
        g_cnt[row] = (c < CAP) ? c : CAP;
        g_dis[row] = rsqrtf((float)(c + 1));           // A_tilde = A + I
    }
}

// =====================================================================
// Kernel 2: ys = dis * (x @ W^T)  (fp16 m16n8k16 mma.sync, fragment-major
// smem, double buffered, 24KB).  dis folded into the epilogue.
// =====================================================================
#define BM 128
#define BN 64
#define BK 32
#define SBUF 3072

__global__ __launch_bounds__(256) void gemm_kernel(const float* __restrict__ x,
                                                   const float* __restrict__ W) {
    __shared__ uint32_t smem[SBUF * 2];               // 24 KB
    const int tid = threadIdx.x;
    const int id = blockIdx.x;
    const int m0 = (id >> 3) * BM;
    const int n0 = (id & 7) * BN;

    const int wid = tid >> 5, lane = tid & 31;
    const int wm = wid & 3;
    const int wn = wid >> 2;
    const int g = lane >> 2, t = lane & 3;

    float acc[2][4][4];
    #pragma unroll
    for (int i = 0; i < 2; i++)
        #pragma unroll
        for (int j = 0; j < 4; j++)
            #pragma unroll
            for (int r = 0; r < 4; r++) acc[i][j][r] = 0.0f;

    float4 pa[4], pb[2];

    auto load_tile = [&](int k0) {
        #pragma unroll
        for (int i = 0; i < 4; i++) {
            int f = tid + i * 256;
            int m = f >> 3, kq = f & 7;
            pa[i] = *reinterpret_cast<const float4*>(&x[(size_t)(m0 + m) * D + k0 + kq * 4]);
        }
        #pragma unroll
        for (int i = 0; i < 2; i++) {
            int f = tid + i * 256;
            int n = f >> 3, kq = f & 7;
            pb[i] = *reinterpret_cast<const float4*>(&W[(size_t)(n0 + n) * D + k0 + kq * 4]);
        }
    };

    auto stage_tile = [&](int buf) {
        uint32_t* sA = smem + buf * SBUF;
        uint32_t* sB = smem + buf * SBUF + 2048;
        #pragma unroll
        for (int i = 0; i < 4; i++) {
            int f = tid + i * 256;
            int m = f >> 3, k0 = (f & 7) * 4;
            const float* p = reinterpret_cast<const float*>(&pa[i]);
            #pragma unroll
            for (int j = 0; j < 2; j++) {
                int k = k0 + 2 * j;
                int ks = k >> 4, mt = m >> 4;
                int ln = (m & 7) * 4 + ((k & 7) >> 1);
                int rg = ((m >> 3) & 1) + (((k >> 3) & 1) << 1);
                __half2 h = __float22half2_rn(make_float2(p[2 * j], p[2 * j + 1]));
                sA[((ks * 8 + mt) * 32 + ln) * 4 + rg] = *reinterpret_cast<uint32_t*>(&h);
            }
        }
        #pragma unroll
        for (int i = 0; i < 2; i++) {
            int f = tid + i * 256;
            int n = f >> 3, k0 = (f & 7) * 4;
            const float* p = reinterpret_cast<const float*>(&pb[i]);
            #pragma unroll
            for (int j = 0; j < 2; j++) {
                int k = k0 + 2 * j;
                int ks = k >> 4, nt = n >> 3;
                int ln = (n & 7) * 4 + ((k & 7) >> 1);
                int rg = (k >> 3) & 1;
                __half2 h = __float22half2_rn(make_float2(p[2 * j], p[2 * j + 1]));
                sB[((ks * 8 + nt) * 32 + ln) * 2 + rg] = *reinterpret_cast<uint32_t*>(&h);
            }
        }
    };

    auto compute = [&](int buf) {
        const uint32_t* sA = smem + buf * SBUF;
        const uint32_t* sB = smem + buf * SBUF + 2048;
        #pragma unroll
        for (int ks = 0; ks < 2; ks++) {
            uint4 afr[2];
            uint2 bfr[4];
            #pragma unroll
            for (int mtl = 0; mtl < 2; mtl++) {
                int slab = ks * 8 + wm * 2 + mtl;
                afr[mtl] = *reinterpret_cast<const uint4*>(&sA[(slab * 32 + lane) * 4]);
            }
            #pragma unroll
            for (int ntl = 0; ntl < 4; ntl++) {
                int slab = ks * 8 + wn * 4 + ntl;
                bfr[ntl] = *reinterpret_cast<const uint2*>(&sB[(slab * 32 + lane) * 2]);
            }
            #pragma unroll
            for (int mtl = 0; mtl < 2; mtl++)
                #pragma unroll
                for (int ntl = 0; ntl < 4; ntl++)
                    mma_fp16(acc[mtl][ntl],
                             reinterpret_cast<const uint32_t*>(&afr[mtl]),
                             reinterpret_cast<const uint32_t*>(&bfr[ntl]));
        }
    };

    load_tile(0);
    stage_tile(0);
    __syncthreads();

    for (int it = 0; it < D / BK; it++) {
        if (it + 1 < D / BK) load_tile((it + 1) * BK);
        compute(it & 1);
        if (it + 1 < D / BK) stage_tile((it + 1) & 1);
        __syncthreads();
    }

    // epilogue: ys = dis[row] * y, stored fp16
    __half* yh = reinterpret_cast<__half*>(g_ys);
    #pragma unroll
    for (int mtl = 0; mtl < 2; mtl++) {
        const int rA = m0 + wm * 32 + mtl * 16 + g;
        const float dA = g_dis[rA];
        const float dB = g_dis[rA + 8];
        #pragma unroll
        for (int ntl = 0; ntl < 4; ntl++) {
            const int cc = n0 + wn * 32 + ntl * 8 + t * 2;
            __half2 lo = __float22half2_rn(
                make_float2(dA * acc[mtl][ntl][0], dA * acc[mtl][ntl][1]));
            __half2 hi = __float22half2_rn(
                make_float2(dB * acc[mtl][ntl][2], dB * acc[mtl][ntl][3]));
            *reinterpret_cast<__half2*>(&yh[(size_t)rA * D + cc])       = lo;
            *reinterpret_cast<__half2*>(&yh[(size_t)(rA + 8) * D + cc]) = hi;
        }
    }
}

// =====================================================================
// Kernel 3: aggregate + bias + relu (unweighted fp16 gather, fp32 acc)
//   out[i,:] = relu( di * ( ys[i,:] + sum_{j in N(i)} ys[j,:] ) + b )
// =====================================================================
__device__ __forceinline__ void acc8(float4& a0, float4& a1, uint4 v) {
    float2 p0 = __half22float2(*reinterpret_cast<__half2*>(&v.x));
    float2 p1 = __half22float2(*reinterpret_cast<__half2*>(&v.y));
    float2 p2 = __half22float2(*reinterpret_cast<__half2*>(&v.z));
    float2 p3 = __half22float2(*reinterpret_cast<__half2*>(&v.w));
    a0.x += p0.x; a0.y += p0.y; a0.z += p1.x; a0.w += p1.y;
    a1.x += p2.x; a1.y += p2.y; a1.z += p3.x; a1.w += p3.y;
}

__global__ __launch_bounds__(64) void aggregate_out_kernel(const float* __restrict__ bias,
                                                           float* __restrict__ out) {
    const int row = blockIdx.x;
    __shared__ int s_nbr[CAP];

    const int cnt = g_cnt[row];
    for (int e = threadIdx.x; e < cnt; e += 64) s_nbr[e] = g_csr[row * CAP + e];
    __syncthreads();

    const int c = threadIdx.x;                         // owns cols [8c, 8c+8)
    float4 a0 = make_float4(0.f, 0.f, 0.f, 0.f);
    float4 a1 = make_float4(0.f, 0.f, 0.f, 0.f);
    acc8(a0, a1, g_ys[row * (D / 8) + c]);             // self term (= ys_i)

    int e = 0;
    for (; e + 4 <= cnt; e += 4) {
        uint4 v0 = g_ys[s_nbr[e + 0] * (D / 8) + c];
        uint4 v1 = g_ys[s_nbr[e + 1] * (D / 8) + c];
        uint4 v2 = g_ys[s_nbr[e + 2] * (D / 8) + c];
        uint4 v3 = g_ys[s_nbr[e + 3] * (D / 8) + c];
        acc8(a0, a1, v0);
        acc8(a0, a1, v1);
        acc8(a0, a1, v2);
        acc8(a0, a1, v3);
    }
    for (; e < cnt; e++) acc8(a0, a1, g_ys[s_nbr[e] * (D / 8) + c]);

    const float di = g_dis[row];
    const float4 b0 = reinterpret_cast<const float4*>(bias)[2 * c];
    const float4 b1 = reinterpret_cast<const float4*>(bias)[2 * c + 1];
    float4 o0, o1;
    o0.x = fmaxf(di * a0.x + b0.x, 0.0f);
    o0.y = fmaxf(di * a0.y + b0.y, 0.0f);
    o0.z = fmaxf(di * a0.z + b0.z, 0.0f);
    o0.w = fmaxf(di * a0.w + b0.w, 0.0f);
    o1.x = fmaxf(di * a1.x + b1.x, 0.0f);
    o1.y = fmaxf(di * a1.y + b1.y, 0.0f);
    o1.z = fmaxf(di * a1.z + b1.z, 0.0f);
    o1.w = fmaxf(di * a1.w + b1.w, 0.0f);
    reinterpret_cast<float4*>(out)[row * (D / 4) + 2 * c]     = o0;
    reinterpret_cast<float4*>(out)[row * (D / 4) + 2 * c + 1] = o1;
}

// =====================================================================
extern "C" void kernel_launch(void* const* d_in, const int* in_sizes, int n_in,
                              void* d_out, int out_size) {
    const float *x = nullptr, *A = nullptr, *W = nullptr, *b = nullptr;
    for (int i = 0; i < n_in; i++) {
        switch (in_sizes[i]) {
            case N_NODES * D:              x = (const float*)d_in[i]; break;
            case 67108864 /* 8192^2 */:    A = (const float*)d_in[i]; break;
            case D * D:                    W = (const float*)d_in[i]; break;
            case D:                        b = (const float*)d_in[i]; break;
        }
    }
    float* out = (float*)d_out;

    build_csr_kernel<<<N_NODES, 256>>>(A);             // writes g_cnt, g_dis
    gemm_kernel<<<(N_NODES / BM) * (D / BN), 256>>>(x, W);  // reads g_dis (epilogue)
    aggregate_out_kernel<<<N_NODES, 64>>>(b, out);
}

// round 13
// speedup vs baseline: 1.0904x; 1.0904x over previous
#include <cuda_runtime.h>
#include <cuda_fp16.h>
#include <cstdint>

#define N_NODES 8192
#define D       512
#define CAP     256

// ---- scratch (device globals) ----
__device__ int    g_csr[N_NODES * CAP];
__device__ int    g_cnt[N_NODES];
__device__ float  g_dis[N_NODES];
__device__ uint4  g_ys[N_NODES * D / 8];   // ys = dis[m] * (x @ W^T)[m], fp16 (8 halves/uint4)

// =====================================================================
// fp16 mma helper (m16n8k16, f32 accumulate) — legacy mma.sync path;
// tcgen05 is unavailable at this bench's compile target (sm_100 virtual).
// =====================================================================
__device__ __forceinline__ void mma_fp16(float* c, const uint32_t* a, const uint32_t* b) {
    asm volatile(
        "mma.sync.aligned.m16n8k16.row.col.f32.f16.f16.f32 "
        "{%0,%1,%2,%3}, {%4,%5,%6,%7}, {%8,%9}, {%0,%1,%2,%3};\n"
        : "+f"(c[0]), "+f"(c[1]), "+f"(c[2]), "+f"(c[3])
        : "r"(a[0]), "r"(a[1]), "r"(a[2]), "r"(a[3]), "r"(b[0]), "r"(b[1]));
}

__device__ __forceinline__ uint32_t packh2(float a, float b) {
    __half2 h = __float22half2_rn(make_float2(a, b));
    return *reinterpret_cast<uint32_t*>(&h);
}

// =====================================================================
// Kernel 1: CSR build — one block per row of dense A.
// Register-prefetch version (R11): 8 batched LDG.128, then scan.
// DRAM 74.7% = the achievable streaming ceiling for this pattern
// (cp.async variant measured identical; reverted).
// =====================================================================
__global__ __launch_bounds__(256) void build_csr_kernel(const float* __restrict__ A) {
    const int row = blockIdx.x;
    __shared__ int s_cnt;
    if (threadIdx.x == 0) s_cnt = 0;
    __syncthreads();

    const float4* Arow = reinterpret_cast<const float4*>(A + (size_t)row * N_NODES);
    int* csr_row = g_csr + row * CAP;

    float4 f[8];
    #pragma unroll
    for (int i = 0; i < 8; i++)
        f[i] = __ldcs(&Arow[threadIdx.x + i * 256]);

    #pragma unroll
    for (int i = 0; i < 8; i++) {
        int base = (threadIdx.x + i * 256) * 4;
        if (f[i].x != 0.0f) { int s = atomicAdd(&s_cnt, 1); if (s < CAP) csr_row[s] = base;     }
        if (f[i].y != 0.0f) { int s = atomicAdd(&s_cnt, 1); if (s < CAP) csr_row[s] = base + 1; }
        if (f[i].z != 0.0f) { int s = atomicAdd(&s_cnt, 1); if (s < CAP) csr_row[s] = base + 2; }
        if (f[i].w != 0.0f) { int s = atomicAdd(&s_cnt, 1); if (s < CAP) csr_row[s] = base + 3; }
    }
    __syncthreads();
    if (threadIdx.x == 0) {
        int c = s_cnt;
        g_cnt[row] = (c < CAP) ? c : CAP;
        g_dis[row] = rsqrtf((float)(c + 1));           // A_tilde = A + I
    }
}

// =====================================================================
// Kernel 2: ys = dis * (x @ W^T)  (fp16 m16n8k16 mma.sync, fragment-major
// smem, double buffered).  BK=64: half the barriers of BK=32, 4x k16
// steps per buffer for latency hiding.  fp32->fp16 conversion at load
// time keeps the prefetch payload at 24 regs.  48KB smem exactly.
// =====================================================================
#define BM 128
#define BN 64
#define BK 64
// per buffer (u32): sA = 4ks*8mt*32lane*4reg = 4096 ; sB = 4ks*8nt*32lane*2reg = 2048
#define SBUF 6144

__global__ __launch_bounds__(256) void gemm_kernel(const float* __restrict__ x,
                                                   const float* __restrict__ W) {
    __shared__ uint32_t smem[SBUF * 2];               // 48 KB exactly
    const int tid = threadIdx.x;
    const int id = blockIdx.x;
    const int m0 = (id >> 3) * BM;
    const int n0 = (id & 7) * BN;

    const int wid = tid >> 5, lane = tid & 31;
    const int wm = wid & 3;
    const int wn = wid >> 2;
    const int g = lane >> 2, t = lane & 3;

    float acc[2][4][4];
    #pragma unroll
    for (int i = 0; i < 2; i++)
        #pragma unroll
        for (int j = 0; j < 4; j++)
            #pragma unroll
            for (int r = 0; r < 4; r++) acc[i][j][r] = 0.0f;

    // prefetch payload: fp16 pairs (converted at load)
    uint32_t pa[16], pb[8];

    auto load_tile = [&](int k0) {
        #pragma unroll
        for (int i = 0; i < 8; i++) {
            int f = tid + i * 256;
            int m = f >> 4, kq = f & 15;               // 16 float4 per 64-col row
            float4 v = *reinterpret_cast<const float4*>(&x[(size_t)(m0 + m) * D + k0 + kq * 4]);
            pa[2 * i]     = packh2(v.x, v.y);
            pa[2 * i + 1] = packh2(v.z, v.w);
        }
        #pragma unroll
        for (int i = 0; i < 4; i++) {
            int f = tid + i * 256;
            int n = f >> 4, kq = f & 15;
            float4 v = *reinterpret_cast<const float4*>(&W[(size_t)(n0 + n) * D + k0 + kq * 4]);
            pb[2 * i]     = packh2(v.x, v.y);
            pb[2 * i + 1] = packh2(v.z, v.w);
        }
    };

    // fragment-major staging (same fragment formulas as BK=32 version,
    // k-field widened to 64)
    auto stage_tile = [&](int buf) {
        uint32_t* sA = smem + buf * SBUF;
        uint32_t* sB = smem + buf * SBUF + 4096;
        #pragma unroll
        for (int i = 0; i < 8; i++) {
            int f = tid + i * 256;
            int m = f >> 4, k0 = (f & 15) * 4;
            #pragma unroll
            for (int j = 0; j < 2; j++) {
                int k = k0 + 2 * j;
                int ks = k >> 4, mt = m >> 4;
                int ln = (m & 7) * 4 + ((k & 7) >> 1);
                int rg = ((m >> 3) & 1) + (((k >> 3) & 1) << 1);
                sA[((ks * 8 + mt) * 32 + ln) * 4 + rg] = pa[2 * i + j];
            }
        }
        #pragma unroll
        for (int i = 0; i < 4; i++) {
            int f = tid + i * 256;
            int n = f >> 4, k0 = (f & 15) * 4;
            #pragma unroll
            for (int j = 0; j < 2; j++) {
                int k = k0 + 2 * j;
                int ks = k >> 4, nt = n >> 3;
                int ln = (n & 7) * 4 + ((k & 7) >> 1);
                int rg = (k >> 3) & 1;
                sB[((ks * 8 + nt) * 32 + ln) * 2 + rg] = pb[2 * i + j];
            }
        }
    };

    auto compute = [&](int buf) {
        const uint32_t* sA = smem + buf * SBUF;
        const uint32_t* sB = smem + buf * SBUF + 4096;
        #pragma unroll
        for (int ks = 0; ks < 4; ks++) {               // 4 x k16 per buffer
            uint4 afr[2];
            uint2 bfr[4];
            #pragma unroll
            for (int mtl = 0; mtl < 2; mtl++) {
                int slab = ks * 8 + wm * 2 + mtl;
                afr[mtl] = *reinterpret_cast<const uint4*>(&sA[(slab * 32 + lane) * 4]);
            }
            #pragma unroll
            for (int ntl = 0; ntl < 4; ntl++) {
                int slab = ks * 8 + wn * 4 + ntl;
                bfr[ntl] = *reinterpret_cast<const uint2*>(&sB[(slab * 32 + lane) * 2]);
            }
            #pragma unroll
            for (int mtl = 0; mtl < 2; mtl++)
                #pragma unroll
                for (int ntl = 0; ntl < 4; ntl++)
                    mma_fp16(acc[mtl][ntl],
                             reinterpret_cast<const uint32_t*>(&afr[mtl]),
                             reinterpret_cast<const uint32_t*>(&bfr[ntl]));
        }
    };

    load_tile(0);
    stage_tile(0);
    __syncthreads();

    for (int it = 0; it < D / BK; it++) {              // 8 iterations
        if (it + 1 < D / BK) load_tile((it + 1) * BK);
        compute(it & 1);
        if (it + 1 < D / BK) stage_tile((it + 1) & 1);
        __syncthreads();
    }

    // epilogue: ys = dis[row] * y, stored fp16
    __half* yh = reinterpret_cast<__half*>(g_ys);
    #pragma unroll
    for (int mtl = 0; mtl < 2; mtl++) {
        const int rA = m0 + wm * 32 + mtl * 16 + g;
        const float dA = g_dis[rA];
        const float dB = g_dis[rA + 8];
        #pragma unroll
        for (int ntl = 0; ntl < 4; ntl++) {
            const int cc = n0 + wn * 32 + ntl * 8 + t * 2;
            __half2 lo = __float22half2_rn(
                make_float2(dA * acc[mtl][ntl][0], dA * acc[mtl][ntl][1]));
            __half2 hi = __float22half2_rn(
                make_float2(dB * acc[mtl][ntl][2], dB * acc[mtl][ntl][3]));
            *reinterpret_cast<__half2*>(&yh[(size_t)rA * D + cc])       = lo;
            *reinterpret_cast<__half2*>(&yh[(size_t)(rA + 8) * D + cc]) = hi;
        }
    }
}

// =====================================================================
// Kernel 3: aggregate + bias + relu (unweighted fp16 gather, fp32 acc)
//   out[i,:] = relu( di * ( ys[i,:] + sum_{j in N(i)} ys[j,:] ) + b )
// At its L2 roofline (~268MB gather @ ~10TB/s); unchanged.
// =====================================================================
__device__ __forceinline__ void acc8(float4& a0, float4& a1, uint4 v) {
    float2 p0 = __half22float2(*reinterpret_cast<__half2*>(&v.x));
    float2 p1 = __half22float2(*reinterpret_cast<__half2*>(&v.y));
    float2 p2 = __half22float2(*reinterpret_cast<__half2*>(&v.z));
    float2 p3 = __half22float2(*reinterpret_cast<__half2*>(&v.w));
    a0.x += p0.x; a0.y += p0.y; a0.z += p1.x; a0.w += p1.y;
    a1.x += p2.x; a1.y += p2.y; a1.z += p3.x; a1.w += p3.y;
}

__global__ __launch_bounds__(64) void aggregate_out_kernel(const float* __restrict__ bias,
                                                           float* __restrict__ out) {
    const int row = blockIdx.x;
    __shared__ int s_nbr[CAP];

    const int cnt = g_cnt[row];
    for (int e = threadIdx.x; e < cnt; e += 64) s_nbr[e] = g_csr[row * CAP + e];
    __syncthreads();

    const int c = threadIdx.x;                         // owns cols [8c, 8c+8)
    float4 a0 = make_float4(0.f, 0.f, 0.f, 0.f);
    float4 a1 = make_float4(0.f, 0.f, 0.f, 0.f);
    acc8(a0, a1, g_ys[row * (D / 8) + c]);             // self term (= ys_i)

    int e = 0;
    for (; e + 4 <= cnt; e += 4) {
        uint4 v0 = g_ys[s_nbr[e + 0] * (D / 8) + c];
        uint4 v1 = g_ys[s_nbr[e + 1] * (D / 8) + c];
        uint4 v2 = g_ys[s_nbr[e + 2] * (D / 8) + c];
        uint4 v3 = g_ys[s_nbr[e + 3] * (D / 8) + c];
        acc8(a0, a1, v0);
        acc8(a0, a1, v1);
        acc8(a0, a1, v2);
        acc8(a0, a1, v3);
    }
    for (; e < cnt; e++) acc8(a0, a1, g_ys[s_nbr[e] * (D / 8) + c]);

    const float di = g_dis[row];
    const float4 b0 = reinterpret_cast<const float4*>(bias)[2 * c];
    const float4 b1 = reinterpret_cast<const float4*>(bias)[2 * c + 1];
    float4 o0, o1;
    o0.x = fmaxf(di * a0.x + b0.x, 0.0f);
    o0.y = fmaxf(di * a0.y + b0.y, 0.0f);
    o0.z = fmaxf(di * a0.z + b0.z, 0.0f);
    o0.w = fmaxf(di * a0.w + b0.w, 0.0f);
    o1.x = fmaxf(di * a1.x + b1.x, 0.0f);
    o1.y = fmaxf(di * a1.y + b1.y, 0.0f);
    o1.z = fmaxf(di * a1.z + b1.z, 0.0f);
    o1.w = fmaxf(di * a1.w + b1.w, 0.0f);
    reinterpret_cast<float4*>(out)[row * (D / 4) + 2 * c]     = o0;
    reinterpret_cast<float4*>(out)[row * (D / 4) + 2 * c + 1] = o1;
}

// =====================================================================
extern "C" void kernel_launch(void* const* d_in, const int* in_sizes, int n_in,
                              void* d_out, int out_size) {
    const float *x = nullptr, *A = nullptr, *W = nullptr, *b = nullptr;
    for (int i = 0; i < n_in; i++) {
        switch (in_sizes[i]) {
            case N_NODES * D:              x = (const float*)d_in[i]; break;
            case 67108864 /* 8192^2 */:    A = (const float*)d_in[i]; break;
            case D * D:                    W = (const float*)d_in[i]; break;
            case D:                        b = (const float*)d_in[i]; break;
        }
    }
    float* out = (float*)d_out;

    build_csr_kernel<<<N_NODES, 256>>>(A);             // writes g_cnt, g_dis
    gemm_kernel<<<(N_NODES / BM) * (D / BN), 256>>>(x, W);  // reads g_dis (epilogue)
    aggregate_out_kernel<<<N_NODES, 64>>>(b, out);
}

// round 14
// speedup vs baseline: 1.2739x; 1.1682x over previous
#include <cuda_runtime.h>
#include <cuda_fp16.h>
#include <cstdint>

#define N_NODES 8192
#define D       512
#define CAP     256
#define XN      (N_NODES * D)
#define WN      (D * D)

// ---- scratch (device globals) ----
__device__ int    g_csr[N_NODES * CAP];
__device__ int    g_cnt[N_NODES];
__device__ float  g_dis[N_NODES];
__device__ uint4  g_ys[N_NODES * D / 8];   // ys = dis[m] * (x @ W^T)[m], fp16
__device__ __half g_xh[XN];                // fp16 copies of x and W (pre-converted)
__device__ __half g_wh[WN];

__device__ __forceinline__ uint32_t smem_u32(const void* p) {
    uint32_t a;
    asm("{ .reg .u64 t; cvta.to.shared.u64 t, %1; cvt.u32.u64 %0, t; }" : "=r"(a) : "l"(p));
    return a;
}
__device__ __forceinline__ uint32_t packh2(float a, float b) {
    __half2 h = __float22half2_rn(make_float2(a, b));
    return *reinterpret_cast<uint32_t*>(&h);
}
__device__ __forceinline__ void mma_fp16(float* c, const uint32_t* a, const uint32_t* b) {
    asm volatile(
        "mma.sync.aligned.m16n8k16.row.col.f32.f16.f16.f32 "
        "{%0,%1,%2,%3}, {%4,%5,%6,%7}, {%8,%9}, {%0,%1,%2,%3};\n"
        : "+f"(c[0]), "+f"(c[1]), "+f"(c[2]), "+f"(c[3])
        : "r"(a[0]), "r"(a[1]), "r"(a[2]), "r"(a[3]), "r"(b[0]), "r"(b[1]));
}
__device__ __forceinline__ void ldsm_x4(uint32_t& r0, uint32_t& r1, uint32_t& r2, uint32_t& r3,
                                        uint32_t addr) {
    asm volatile("ldmatrix.sync.aligned.m8n8.x4.shared.b16 {%0,%1,%2,%3}, [%4];"
                 : "=r"(r0), "=r"(r1), "=r"(r2), "=r"(r3) : "r"(addr));
}

// =====================================================================
// Kernel 0: pre-convert x and W to fp16 (8 floats / thread)
// =====================================================================
__global__ __launch_bounds__(256) void convert_kernel(const float* __restrict__ x,
                                                      const float* __restrict__ W) {
    int idx = blockIdx.x * 256 + threadIdx.x;
    const float4* s;
    uint4* d;
    if (idx < XN / 8) { s = reinterpret_cast<const float4*>(x); d = reinterpret_cast<uint4*>(g_xh); }
    else { s = reinterpret_cast<const float4*>(W); d = reinterpret_cast<uint4*>(g_wh); idx -= XN / 8; }
    float4 v0 = s[idx * 2], v1 = s[idx * 2 + 1];
    uint4 o;
    o.x = packh2(v0.x, v0.y); o.y = packh2(v0.z, v0.w);
    o.z = packh2(v1.x, v1.y); o.w = packh2(v1.z, v1.w);
    d[idx] = o;
}

// =====================================================================
// Kernel 1: CSR build (register-prefetch version; DRAM ~75% = ceiling)
// =====================================================================
__global__ __launch_bounds__(256) void build_csr_kernel(const float* __restrict__ A) {
    const int row = blockIdx.x;
    __shared__ int s_cnt;
    if (threadIdx.x == 0) s_cnt = 0;
    __syncthreads();

    const float4* Arow = reinterpret_cast<const float4*>(A + (size_t)row * N_NODES);
    int* csr_row = g_csr + row * CAP;

    float4 f[8];
    #pragma unroll
    for (int i = 0; i < 8; i++)
        f[i] = __ldcs(&Arow[threadIdx.x + i * 256]);

    #pragma unroll
    for (int i = 0; i < 8; i++) {
        int base = (threadIdx.x + i * 256) * 4;
        if (f[i].x != 0.0f) { int s = atomicAdd(&s_cnt, 1); if (s < CAP) csr_row[s] = base;     }
        if (f[i].y != 0.0f) { int s = atomicAdd(&s_cnt, 1); if (s < CAP) csr_row[s] = base + 1; }
        if (f[i].z != 0.0f) { int s = atomicAdd(&s_cnt, 1); if (s < CAP) csr_row[s] = base + 2; }
        if (f[i].w != 0.0f) { int s = atomicAdd(&s_cnt, 1); if (s < CAP) csr_row[s] = base + 3; }
    }
    __syncthreads();
    if (threadIdx.x == 0) {
        int c = s_cnt;
        g_cnt[row] = (c < CAP) ? c : CAP;
        g_dis[row] = rsqrtf((float)(c + 1));           // A_tilde = A + I
    }
}

// =====================================================================
// Kernel 2: ys = dis * (xh @ Wh^T)  — cp.async + ldmatrix pipeline.
// BM=128, BN=64, BK=64, 2 stages x 24KB = 48KB.  XOR swizzle
// (chunk ^= row&7) makes cp.async stores and LDSM reads conflict-free.
// =====================================================================
#define BM 128
#define BN 64
#define BK 64
#define STAGE_BYTES 24576   // A 16KB + B 8KB

__global__ __launch_bounds__(256) void gemm_kernel() {
    __shared__ __align__(16) uint32_t smem[2 * STAGE_BYTES / 4];
    const uint32_t sbase = smem_u32(smem);
    const int tid = threadIdx.x;
    const int id = blockIdx.x;
    const int m0 = (id >> 3) * BM;
    const int n0 = (id & 7) * BN;

    const int wid = tid >> 5, lane = tid & 31;
    const int wm = wid & 3;                            // 4 warps in M
    const int wn = wid >> 2;                           // 2 warps in N
    const int g8 = lane & 7, q = lane >> 3;            // ldmatrix lane decomposition

    float acc[2][4][4];
    #pragma unroll
    for (int i = 0; i < 2; i++)
        #pragma unroll
        for (int j = 0; j < 4; j++)
            #pragma unroll
            for (int r = 0; r < 4; r++) acc[i][j][r] = 0.0f;

    auto issue_stage = [&](int stage, int k0) {
        const uint32_t sA = sbase + stage * STAGE_BYTES;
        const uint32_t sB = sA + 16384;
        #pragma unroll
        for (int i = 0; i < 4; i++) {                  // A: 1024 chunks of 16B
            int cid = tid + i * 256;
            int row = cid >> 3, c = cid & 7;
            uint32_t dst = sA + row * 128 + ((c ^ (row & 7)) << 4);
            asm volatile("cp.async.cg.shared.global [%0], [%1], 16;"
                         :: "r"(dst), "l"(&g_xh[(size_t)(m0 + row) * D + k0 + c * 8]) : "memory");
        }
        #pragma unroll
        for (int i = 0; i < 2; i++) {                  // B: 512 chunks
            int cid = tid + i * 256;
            int row = cid >> 3, c = cid & 7;
            uint32_t dst = sB + row * 128 + ((c ^ (row & 7)) << 4);
            asm volatile("cp.async.cg.shared.global [%0], [%1], 16;"
                         :: "r"(dst), "l"(&g_wh[(size_t)(n0 + row) * D + k0 + c * 8]) : "memory");
        }
        asm volatile("cp.async.commit_group;" ::: "memory");
    };

    auto compute = [&](int stage) {
        const uint32_t sA = sbase + stage * STAGE_BYTES;
        const uint32_t sB = sA + 16384;
        #pragma unroll
        for (int ks = 0; ks < 4; ks++) {               // 4 x k16 per BK=64
            uint32_t a[2][4];
            #pragma unroll
            for (int mtl = 0; mtl < 2; mtl++) {
                int row = wm * 32 + mtl * 16 + g8 + ((q & 1) << 3);
                int c = ks * 2 + (q >> 1);
                uint32_t addr = sA + row * 128 + ((c ^ (row & 7)) << 4);
                ldsm_x4(a[mtl][0], a[mtl][1], a[mtl][2], a[mtl][3], addr);
            }
            #pragma unroll
            for (int h = 0; h < 2; h++) {              // pairs of n-tiles
                uint32_t b0, b1, b2, b3;
                int nrow = wn * 32 + (2 * h + (q >> 1)) * 8 + g8;
                int c = ks * 2 + (q & 1);
                uint32_t addr = sB + nrow * 128 + ((c ^ (nrow & 7)) << 4);
                ldsm_x4(b0, b1, b2, b3, addr);
                uint32_t bl[2] = {b0, b1}, bh[2] = {b2, b3};
                mma_fp16(acc[0][2 * h],     a[0], bl);
                mma_fp16(acc[0][2 * h + 1], a[0], bh);
                mma_fp16(acc[1][2 * h],     a[1], bl);
                mma_fp16(acc[1][2 * h + 1], a[1], bh);
            }
        }
    };

    issue_stage(0, 0);
    issue_stage(1, BK);
    for (int it = 0; it < D / BK; it++) {              // 8 iterations
        asm volatile("cp.async.wait_group 1;" ::: "memory");
        __syncthreads();
        compute(it & 1);
        __syncthreads();
        if (it < D / BK - 2) issue_stage(it & 1, (it + 2) * BK);
        else asm volatile("cp.async.commit_group;" ::: "memory");  // keep group count
    }

    // epilogue: ys = dis[row] * y, stored fp16
    const int eg = lane >> 2, et = lane & 3;
    __half* yh = reinterpret_cast<__half*>(g_ys);
    #pragma unroll
    for (int mtl = 0; mtl < 2; mtl++) {
        const int rA = m0 + wm * 32 + mtl * 16 + eg;
        const float dA = g_dis[rA];
        const float dB = g_dis[rA + 8];
        #pragma unroll
        for (int ntl = 0; ntl < 4; ntl++) {
            const int cc = n0 + wn * 32 + ntl * 8 + et * 2;
            __half2 lo = __float22half2_rn(
                make_float2(dA * acc[mtl][ntl][0], dA * acc[mtl][ntl][1]));
            __half2 hi = __float22half2_rn(
                make_float2(dB * acc[mtl][ntl][2], dB * acc[mtl][ntl][3]));
            *reinterpret_cast<__half2*>(&yh[(size_t)rA * D + cc])       = lo;
            *reinterpret_cast<__half2*>(&yh[(size_t)(rA + 8) * D + cc]) = hi;
        }
    }
}

// =====================================================================
// Kernel 3: aggregate + bias + relu (unweighted fp16 gather, fp32 acc)
// =====================================================================
__device__ __forceinline__ void acc8(float4& a0, float4& a1, uint4 v) {
    float2 p0 = __half22float2(*reinterpret_cast<__half2*>(&v.x));
    float2 p1 = __half22float2(*reinterpret_cast<__half2*>(&v.y));
    float2 p2 = __half22float2(*reinterpret_cast<__half2*>(&v.z));
    float2 p3 = __half22float2(*reinterpret_cast<__half2*>(&v.w));
    a0.x += p0.x; a0.y += p0.y; a0.z += p1.x; a0.w += p1.y;
    a1.x += p2.x; a1.y += p2.y; a1.z += p3.x; a1.w += p3.y;
}

__global__ __launch_bounds__(64) void aggregate_out_kernel(const float* __restrict__ bias,
                                                           float* __restrict__ out) {
    const int row = blockIdx.x;
    __shared__ int s_nbr[CAP];

    const int cnt = g_cnt[row];
    for (int e = threadIdx.x; e < cnt; e += 64) s_nbr[e] = g_csr[row * CAP + e];
    __syncthreads();

    const int c = threadIdx.x;                         // owns cols [8c, 8c+8)
    float4 a0 = make_float4(0.f, 0.f, 0.f, 0.f);
    float4 a1 = make_float4(0.f, 0.f, 0.f, 0.f);
    acc8(a0, a1, g_ys[row * (D / 8) + c]);             // self term

    int e = 0;
    for (; e + 4 <= cnt; e += 4) {
        uint4 v0 = g_ys[s_nbr[e + 0] * (D / 8) + c];
        uint4 v1 = g_ys[s_nbr[e + 1] * (D / 8) + c];
        uint4 v2 = g_ys[s_nbr[e + 2] * (D / 8) + c];
        uint4 v3 = g_ys[s_nbr[e + 3] * (D / 8) + c];
        acc8(a0, a1, v0);
        acc8(a0, a1, v1);
        acc8(a0, a1, v2);
        acc8(a0, a1, v3);
    }
    for (; e < cnt; e++) acc8(a0, a1, g_ys[s_nbr[e] * (D / 8) + c]);

    const float di = g_dis[row];
    const float4 b0 = reinterpret_cast<const float4*>(bias)[2 * c];
    const float4 b1 = reinterpret_cast<const float4*>(bias)[2 * c + 1];
    float4 o0, o1;
    o0.x = fmaxf(di * a0.x + b0.x, 0.0f);
    o0.y = fmaxf(di * a0.y + b0.y, 0.0f);
    o0.z = fmaxf(di * a0.z + b0.z, 0.0f);
    o0.w = fmaxf(di * a0.w + b0.w, 0.0f);
    o1.x = fmaxf(di * a1.x + b1.x, 0.0f);
    o1.y = fmaxf(di * a1.y + b1.y, 0.0f);
    o1.z = fmaxf(di * a1.z + b1.z, 0.0f);
    o1.w = fmaxf(di * a1.w + b1.w, 0.0f);
    reinterpret_cast<float4*>(out)[row * (D / 4) + 2 * c]     = o0;
    reinterpret_cast<float4*>(out)[row * (D / 4) + 2 * c + 1] = o1;
}

// =====================================================================
extern "C" void kernel_launch(void* const* d_in, const int* in_sizes, int n_in,
                              void* d_out, int out_size) {
    const float *x = nullptr, *A = nullptr, *W = nullptr, *b = nullptr;
    for (int i = 0; i < n_in; i++) {
        switch (in_sizes[i]) {
            case XN:                       x = (const float*)d_in[i]; break;
            case 67108864 /* 8192^2 */:    A = (const float*)d_in[i]; break;
            case WN:                       W = (const float*)d_in[i]; break;
            case D:                        b = (const float*)d_in[i]; break;
        }
    }
    float* out = (float*)d_out;

    convert_kernel<<<(XN + WN) / 8 / 256, 256>>>(x, W);
    build_csr_kernel<<<N_NODES, 256>>>(A);             // writes g_cnt, g_dis
    gemm_kernel<<<(N_NODES / BM) * (D / BN), 256>>>();
    aggregate_out_kernel<<<N_NODES, 64>>>(b, out);
}

// round 15
// speedup vs baseline: 1.3026x; 1.0226x over previous
#include <cuda_runtime.h>
#include <cuda_fp16.h>
#include <cstdint>

#define N_NODES 8192
#define D       512
#define CAP     256
#define XN      (N_NODES * D)
#define WN      (D * D)

// ---- scratch (device globals) ----
__device__ int    g_csr[N_NODES * CAP];
__device__ int    g_cnt[N_NODES];
__device__ float  g_dis[N_NODES];
__device__ uint4  g_ys[N_NODES * D / 8];   // ys = dis[m] * (x @ W^T)[m], fp16
__device__ __half g_xh[XN];                // fp16 copies of x and W (pre-converted)
__device__ __half g_wh[WN];

__device__ __forceinline__ uint32_t smem_u32(const void* p) {
    uint32_t a;
    asm("{ .reg .u64 t; cvta.to.shared.u64 t, %1; cvt.u32.u64 %0, t; }" : "=r"(a) : "l"(p));
    return a;
}
__device__ __forceinline__ uint32_t packh2(float a, float b) {
    __half2 h = __float22half2_rn(make_float2(a, b));
    return *reinterpret_cast<uint32_t*>(&h);
}
__device__ __forceinline__ void mma_fp16(float* c, const uint32_t* a, const uint32_t* b) {
    asm volatile(
        "mma.sync.aligned.m16n8k16.row.col.f32.f16.f16.f32 "
        "{%0,%1,%2,%3}, {%4,%5,%6,%7}, {%8,%9}, {%0,%1,%2,%3};\n"
        : "+f"(c[0]), "+f"(c[1]), "+f"(c[2]), "+f"(c[3])
        : "r"(a[0]), "r"(a[1]), "r"(a[2]), "r"(a[3]), "r"(b[0]), "r"(b[1]));
}
__device__ __forceinline__ void ldsm_x4(uint32_t& r0, uint32_t& r1, uint32_t& r2, uint32_t& r3,
                                        uint32_t addr) {
    asm volatile("ldmatrix.sync.aligned.m8n8.x4.shared.b16 {%0,%1,%2,%3}, [%4];"
                 : "=r"(r0), "=r"(r1), "=r"(r2), "=r"(r3) : "r"(addr));
}

// =====================================================================
// Kernel 0: pre-convert x and W to fp16 (8 floats / thread)
// =====================================================================
__global__ __launch_bounds__(256) void convert_kernel(const float* __restrict__ x,
                                                      const float* __restrict__ W) {
    int idx = blockIdx.x * 256 + threadIdx.x;
    const float4* s;
    uint4* d;
    if (idx < XN / 8) { s = reinterpret_cast<const float4*>(x); d = reinterpret_cast<uint4*>(g_xh); }
    else { s = reinterpret_cast<const float4*>(W); d = reinterpret_cast<uint4*>(g_wh); idx -= XN / 8; }
    float4 v0 = s[idx * 2], v1 = s[idx * 2 + 1];
    uint4 o;
    o.x = packh2(v0.x, v0.y); o.y = packh2(v0.z, v0.w);
    o.z = packh2(v1.x, v1.y); o.w = packh2(v1.z, v1.w);
    d[idx] = o;
}

// =====================================================================
// Kernel 1: CSR build (register-prefetch version; DRAM ~75% = ceiling)
// =====================================================================
__global__ __launch_bounds__(256) void build_csr_kernel(const float* __restrict__ A) {
    const int row = blockIdx.x;
    __shared__ int s_cnt;
    if (threadIdx.x == 0) s_cnt = 0;
    __syncthreads();

    const float4* Arow = reinterpret_cast<const float4*>(A + (size_t)row * N_NODES);
    int* csr_row = g_csr + row * CAP;

    float4 f[8];
    #pragma unroll
    for (int i = 0; i < 8; i++)
        f[i] = __ldcs(&Arow[threadIdx.x + i * 256]);

    #pragma unroll
    for (int i = 0; i < 8; i++) {
        int base = (threadIdx.x + i * 256) * 4;
        if (f[i].x != 0.0f) { int s = atomicAdd(&s_cnt, 1); if (s < CAP) csr_row[s] = base;     }
        if (f[i].y != 0.0f) { int s = atomicAdd(&s_cnt, 1); if (s < CAP) csr_row[s] = base + 1; }
        if (f[i].z != 0.0f) { int s = atomicAdd(&s_cnt, 1); if (s < CAP) csr_row[s] = base + 2; }
        if (f[i].w != 0.0f) { int s = atomicAdd(&s_cnt, 1); if (s < CAP) csr_row[s] = base + 3; }
    }
    __syncthreads();
    if (threadIdx.x == 0) {
        int c = s_cnt;
        g_cnt[row] = (c < CAP) ? c : CAP;
        g_dis[row] = rsqrtf((float)(c + 1));           // A_tilde = A + I
    }
}

// =====================================================================
// Kernel 2: ys = dis * (xh @ Wh^T)  — cp.async + ldmatrix pipeline.
// =====================================================================
#define BM 128
#define BN 64
#define BK 64
#define STAGE_BYTES 24576   // A 16KB + B 8KB

__global__ __launch_bounds__(256) void gemm_kernel() {
    __shared__ __align__(16) uint32_t smem[2 * STAGE_BYTES / 4];
    const uint32_t sbase = smem_u32(smem);
    const int tid = threadIdx.x;
    const int id = blockIdx.x;
    const int m0 = (id >> 3) * BM;
    const int n0 = (id & 7) * BN;

    const int wid = tid >> 5, lane = tid & 31;
    const int wm = wid & 3;                            // 4 warps in M
    const int wn = wid >> 2;                           // 2 warps in N
    const int g8 = lane & 7, q = lane >> 3;            // ldmatrix lane decomposition

    float acc[2][4][4];
    #pragma unroll
    for (int i = 0; i < 2; i++)
        #pragma unroll
        for (int j = 0; j < 4; j++)
            #pragma unroll
            for (int r = 0; r < 4; r++) acc[i][j][r] = 0.0f;

    auto issue_stage = [&](int stage, int k0) {
        const uint32_t sA = sbase + stage * STAGE_BYTES;
        const uint32_t sB = sA + 16384;
        #pragma unroll
        for (int i = 0; i < 4; i++) {                  // A: 1024 chunks of 16B
            int cid = tid + i * 256;
            int row = cid >> 3, c = cid & 7;
            uint32_t dst = sA + row * 128 + ((c ^ (row & 7)) << 4);
            asm volatile("cp.async.cg.shared.global [%0], [%1], 16;"
                         :: "r"(dst), "l"(&g_xh[(size_t)(m0 + row) * D + k0 + c * 8]) : "memory");
        }
        #pragma unroll
        for (int i = 0; i < 2; i++) {                  // B: 512 chunks
            int cid = tid + i * 256;
            int row = cid >> 3, c = cid & 7;
            uint32_t dst = sB + row * 128 + ((c ^ (row & 7)) << 4);
            asm volatile("cp.async.cg.shared.global [%0], [%1], 16;"
                         :: "r"(dst), "l"(&g_wh[(size_t)(n0 + row) * D + k0 + c * 8]) : "memory");
        }
        asm volatile("cp.async.commit_group;" ::: "memory");
    };

    auto compute = [&](int stage) {
        const uint32_t sA = sbase + stage * STAGE_BYTES;
        const uint32_t sB = sA + 16384;
        #pragma unroll
        for (int ks = 0; ks < 4; ks++) {               // 4 x k16 per BK=64
            uint32_t a[2][4];
            #pragma unroll
            for (int mtl = 0; mtl < 2; mtl++) {
                int row = wm * 32 + mtl * 16 + g8 + ((q & 1) << 3);
                int c = ks * 2 + (q >> 1);
                uint32_t addr = sA + row * 128 + ((c ^ (row & 7)) << 4);
                ldsm_x4(a[mtl][0], a[mtl][1], a[mtl][2], a[mtl][3], addr);
            }
            #pragma unroll
            for (int h = 0; h < 2; h++) {              // pairs of n-tiles
                uint32_t b0, b1, b2, b3;
                int nrow = wn * 32 + (2 * h + (q >> 1)) * 8 + g8;
                int c = ks * 2 + (q & 1);
                uint32_t addr = sB + nrow * 128 + ((c ^ (nrow & 7)) << 4);
                ldsm_x4(b0, b1, b2, b3, addr);
                uint32_t bl[2] = {b0, b1}, bh[2] = {b2, b3};
                mma_fp16(acc[0][2 * h],     a[0], bl);
                mma_fp16(acc[0][2 * h + 1], a[0], bh);
                mma_fp16(acc[1][2 * h],     a[1], bl);
                mma_fp16(acc[1][2 * h + 1], a[1], bh);
            }
        }
    };

    issue_stage(0, 0);
    issue_stage(1, BK);
    for (int it = 0; it < D / BK; it++) {              // 8 iterations
        asm volatile("cp.async.wait_group 1;" ::: "memory");
        __syncthreads();
        compute(it & 1);
        __syncthreads();
        if (it < D / BK - 2) issue_stage(it & 1, (it + 2) * BK);
        else asm volatile("cp.async.commit_group;" ::: "memory");  // keep group count
    }

    // epilogue: ys = dis[row] * y, stored fp16
    const int eg = lane >> 2, et = lane & 3;
    __half* yh = reinterpret_cast<__half*>(g_ys);
    #pragma unroll
    for (int mtl = 0; mtl < 2; mtl++) {
        const int rA = m0 + wm * 32 + mtl * 16 + eg;
        const float dA = g_dis[rA];
        const float dB = g_dis[rA + 8];
        #pragma unroll
        for (int ntl = 0; ntl < 4; ntl++) {
            const int cc = n0 + wn * 32 + ntl * 8 + et * 2;
            __half2 lo = __float22half2_rn(
                make_float2(dA * acc[mtl][ntl][0], dA * acc[mtl][ntl][1]));
            __half2 hi = __float22half2_rn(
                make_float2(dB * acc[mtl][ntl][2], dB * acc[mtl][ntl][3]));
            *reinterpret_cast<__half2*>(&yh[(size_t)rA * D + cc])       = lo;
            *reinterpret_cast<__half2*>(&yh[(size_t)(rA + 8) * D + cc]) = hi;
        }
    }
}

// =====================================================================
// Kernel 3: aggregate + bias + relu.
// Two-level accumulation: HADD2 in half2 for groups of 8 edges
// (4 ops/edge instead of 16), flushed to fp32 per group.  R14 profile:
// issue 62% / fma 37% -> conversion tax was the binding constraint.
// =====================================================================
__device__ __forceinline__ void acc8f(float4& a0, float4& a1, uint4 v) {
    float2 p0 = __half22float2(*reinterpret_cast<__half2*>(&v.x));
    float2 p1 = __half22float2(*reinterpret_cast<__half2*>(&v.y));
    float2 p2 = __half22float2(*reinterpret_cast<__half2*>(&v.z));
    float2 p3 = __half22float2(*reinterpret_cast<__half2*>(&v.w));
    a0.x += p0.x; a0.y += p0.y; a0.z += p1.x; a0.w += p1.y;
    a1.x += p2.x; a1.y += p2.y; a1.z += p3.x; a1.w += p3.y;
}

__global__ __launch_bounds__(64) void aggregate_out_kernel(const float* __restrict__ bias,
                                                           float* __restrict__ out) {
    const int row = blockIdx.x;
    __shared__ int s_nbr[CAP];

    const int cnt = g_cnt[row];
    for (int e = threadIdx.x; e < cnt; e += 64) s_nbr[e] = g_csr[row * CAP + e];
    __syncthreads();

    const int c = threadIdx.x;                         // owns cols [8c, 8c+8)
    float4 a0 = make_float4(0.f, 0.f, 0.f, 0.f);
    float4 a1 = make_float4(0.f, 0.f, 0.f, 0.f);
    acc8f(a0, a1, g_ys[row * (D / 8) + c]);            // self term (fp32 path)

    int e = 0;
    for (; e + 8 <= cnt; e += 8) {
        __half2 h0 = __floats2half2_rn(0.f, 0.f);
        __half2 h1 = h0, h2 = h0, h3 = h0;
        #pragma unroll
        for (int u = 0; u < 8; u++) {
            uint4 v = g_ys[s_nbr[e + u] * (D / 8) + c];
            h0 = __hadd2(h0, *reinterpret_cast<__half2*>(&v.x));
            h1 = __hadd2(h1, *reinterpret_cast<__half2*>(&v.y));
            h2 = __hadd2(h2, *reinterpret_cast<__half2*>(&v.z));
            h3 = __hadd2(h3, *reinterpret_cast<__half2*>(&v.w));
        }
        float2 f0 = __half22float2(h0), f1 = __half22float2(h1);
        float2 f2 = __half22float2(h2), f3 = __half22float2(h3);
        a0.x += f0.x; a0.y += f0.y; a0.z += f1.x; a0.w += f1.y;
        a1.x += f2.x; a1.y += f2.y; a1.z += f3.x; a1.w += f3.y;
    }
    for (; e < cnt; e++) acc8f(a0, a1, g_ys[s_nbr[e] * (D / 8) + c]);

    const float di = g_dis[row];
    const float4 b0 = reinterpret_cast<const float4*>(bias)[2 * c];
    const float4 b1 = reinterpret_cast<const float4*>(bias)[2 * c + 1];
    float4 o0, o1;
    o0.x = fmaxf(di * a0.x + b0.x, 0.0f);
    o0.y = fmaxf(di * a0.y + b0.y, 0.0f);
    o0.z = fmaxf(di * a0.z + b0.z, 0.0f);
    o0.w = fmaxf(di * a0.w + b0.w, 0.0f);
    o1.x = fmaxf(di * a1.x + b1.x, 0.0f);
    o1.y = fmaxf(di * a1.y + b1.y, 0.0f);
    o1.z = fmaxf(di * a1.z + b1.z, 0.0f);
    o1.w = fmaxf(di * a1.w + b1.w, 0.0f);
    reinterpret_cast<float4*>(out)[row * (D / 4) + 2 * c]     = o0;
    reinterpret_cast<float4*>(out)[row * (D / 4) + 2 * c + 1] = o1;
}

// =====================================================================
extern "C" void kernel_launch(void* const* d_in, const int* in_sizes, int n_in,
                              void* d_out, int out_size) {
    const float *x = nullptr, *A = nullptr, *W = nullptr, *b = nullptr;
    for (int i = 0; i < n_in; i++) {
        switch (in_sizes[i]) {
            case XN:                       x = (const float*)d_in[i]; break;
            case 67108864 /* 8192^2 */:    A = (const float*)d_in[i]; break;
            case WN:                       W = (const float*)d_in[i]; break;
            case D:                        b = (const float*)d_in[i]; break;
        }
    }
    float* out = (float*)d_out;

    convert_kernel<<<(XN + WN) / 8 / 256, 256>>>(x, W);
    build_csr_kernel<<<N_NODES, 256>>>(A);             // writes g_cnt, g_dis
    gemm_kernel<<<(N_NODES / BM) * (D / BN), 256>>>();
    aggregate_out_kernel<<<N_NODES, 64>>>(b, out);
}

// round 16
// speedup vs baseline: 1.3383x; 1.0274x over previous
#include <cuda_runtime.h>
#include <cuda_fp16.h>
#include <cstdint>

#define N_NODES 8192
#define D       512
#define CAP     256
#define XN      (N_NODES * D)
#define WN      (D * D)

// ---- scratch (device globals) ----
__device__ int    g_csr[N_NODES * CAP];
__device__ int    g_cnt[N_NODES];
__device__ float  g_dis[N_NODES];
__device__ uint4  g_ys[N_NODES * D / 8];   // ys = dis[m] * (x @ W^T)[m], fp16
__device__ __half g_xh[XN];                // fp16 copies of x and W (pre-converted)
__device__ __half g_wh[WN];

__device__ __forceinline__ uint32_t smem_u32(const void* p) {
    uint32_t a;
    asm("{ .reg .u64 t; cvta.to.shared.u64 t, %1; cvt.u32.u64 %0, t; }" : "=r"(a) : "l"(p));
    return a;
}
__device__ __forceinline__ uint32_t packh2(float a, float b) {
    __half2 h = __float22half2_rn(make_float2(a, b));
    return *reinterpret_cast<uint32_t*>(&h);
}
__device__ __forceinline__ void mma_fp16(float* c, const uint32_t* a, const uint32_t* b) {
    asm volatile(
        "mma.sync.aligned.m16n8k16.row.col.f32.f16.f16.f32 "
        "{%0,%1,%2,%3}, {%4,%5,%6,%7}, {%8,%9}, {%0,%1,%2,%3};\n"
        : "+f"(c[0]), "+f"(c[1]), "+f"(c[2]), "+f"(c[3])
        : "r"(a[0]), "r"(a[1]), "r"(a[2]), "r"(a[3]), "r"(b[0]), "r"(b[1]));
}
__device__ __forceinline__ void ldsm_x4(uint32_t& r0, uint32_t& r1, uint32_t& r2, uint32_t& r3,
                                        uint32_t addr) {
    asm volatile("ldmatrix.sync.aligned.m8n8.x4.shared.b16 {%0,%1,%2,%3}, [%4];"
                 : "=r"(r0), "=r"(r1), "=r"(r2), "=r"(r3) : "r"(addr));
}

// =====================================================================
// Kernel 0: pre-convert x and W to fp16 (8 floats / thread)
// =====================================================================
__global__ __launch_bounds__(256) void convert_kernel(const float* __restrict__ x,
                                                      const float* __restrict__ W) {
    int idx = blockIdx.x * 256 + threadIdx.x;
    const float4* s;
    uint4* d;
    if (idx < XN / 8) { s = reinterpret_cast<const float4*>(x); d = reinterpret_cast<uint4*>(g_xh); }
    else { s = reinterpret_cast<const float4*>(W); d = reinterpret_cast<uint4*>(g_wh); idx -= XN / 8; }
    float4 v0 = s[idx * 2], v1 = s[idx * 2 + 1];
    uint4 o;
    o.x = packh2(v0.x, v0.y); o.y = packh2(v0.z, v0.w);
    o.z = packh2(v1.x, v1.y); o.w = packh2(v1.z, v1.w);
    d[idx] = o;
}

// =====================================================================
// Kernel 1: CSR build — one block (512 threads) per row of dense A.
// MLP/occupancy rebalance: 4 batched LDG.128 per thread (~26 regs, no
// occupancy cap) instead of 8 (40 regs, occ 70%).  Outstanding bytes =
// occ x MLP; R10/R11 showed both extremes lose.
// =====================================================================
__global__ __launch_bounds__(512) void build_csr_kernel(const float* __restrict__ A) {
    const int row = blockIdx.x;
    __shared__ int s_cnt;
    if (threadIdx.x == 0) s_cnt = 0;
    __syncthreads();

    const float4* Arow = reinterpret_cast<const float4*>(A + (size_t)row * N_NODES);
    int* csr_row = g_csr + row * CAP;

    float4 f[4];
    #pragma unroll
    for (int i = 0; i < 4; i++)
        f[i] = __ldcs(&Arow[threadIdx.x + i * 512]);

    #pragma unroll
    for (int i = 0; i < 4; i++) {
        int base = (threadIdx.x + i * 512) * 4;
        if (f[i].x != 0.0f) { int s = atomicAdd(&s_cnt, 1); if (s < CAP) csr_row[s] = base;     }
        if (f[i].y != 0.0f) { int s = atomicAdd(&s_cnt, 1); if (s < CAP) csr_row[s] = base + 1; }
        if (f[i].z != 0.0f) { int s = atomicAdd(&s_cnt, 1); if (s < CAP) csr_row[s] = base + 2; }
        if (f[i].w != 0.0f) { int s = atomicAdd(&s_cnt, 1); if (s < CAP) csr_row[s] = base + 3; }
    }
    __syncthreads();
    if (threadIdx.x == 0) {
        int c = s_cnt;
        g_cnt[row] = (c < CAP) ? c : CAP;
        g_dis[row] = rsqrtf((float)(c + 1));           // A_tilde = A + I
    }
}

// =====================================================================
// Kernel 2: ys = dis * (xh @ Wh^T)  — cp.async + ldmatrix pipeline.
// =====================================================================
#define BM 128
#define BN 64
#define BK 64
#define STAGE_BYTES 24576   // A 16KB + B 8KB

__global__ __launch_bounds__(256) void gemm_kernel() {
    __shared__ __align__(16) uint32_t smem[2 * STAGE_BYTES / 4];
    const uint32_t sbase = smem_u32(smem);
    const int tid = threadIdx.x;
    const int id = blockIdx.x;
    const int m0 = (id >> 3) * BM;
    const int n0 = (id & 7) * BN;

    const int wid = tid >> 5, lane = tid & 31;
    const int wm = wid & 3;                            // 4 warps in M
    const int wn = wid >> 2;                           // 2 warps in N
    const int g8 = lane & 7, q = lane >> 3;            // ldmatrix lane decomposition

    float acc[2][4][4];
    #pragma unroll
    for (int i = 0; i < 2; i++)
        #pragma unroll
        for (int j = 0; j < 4; j++)
            #pragma unroll
            for (int r = 0; r < 4; r++) acc[i][j][r] = 0.0f;

    auto issue_stage = [&](int stage, int k0) {
        const uint32_t sA = sbase + stage * STAGE_BYTES;
        const uint32_t sB = sA + 16384;
        #pragma unroll
        for (int i = 0; i < 4; i++) {                  // A: 1024 chunks of 16B
            int cid = tid + i * 256;
            int row = cid >> 3, c = cid & 7;
            uint32_t dst = sA + row * 128 + ((c ^ (row & 7)) << 4);
            asm volatile("cp.async.cg.shared.global [%0], [%1], 16;"
                         :: "r"(dst), "l"(&g_xh[(size_t)(m0 + row) * D + k0 + c * 8]) : "memory");
        }
        #pragma unroll
        for (int i = 0; i < 2; i++) {                  // B: 512 chunks
            int cid = tid + i * 256;
            int row = cid >> 3, c = cid & 7;
            uint32_t dst = sB + row * 128 + ((c ^ (row & 7)) << 4);
            asm volatile("cp.async.cg.shared.global [%0], [%1], 16;"
                         :: "r"(dst), "l"(&g_wh[(size_t)(n0 + row) * D + k0 + c * 8]) : "memory");
        }
        asm volatile("cp.async.commit_group;" ::: "memory");
    };

    auto compute = [&](int stage) {
        const uint32_t sA = sbase + stage * STAGE_BYTES;
        const uint32_t sB = sA + 16384;
        #pragma unroll
        for (int ks = 0; ks < 4; ks++) {               // 4 x k16 per BK=64
            uint32_t a[2][4];
            #pragma unroll
            for (int mtl = 0; mtl < 2; mtl++) {
                int row = wm * 32 + mtl * 16 + g8 + ((q & 1) << 3);
                int c = ks * 2 + (q >> 1);
                uint32_t addr = sA + row * 128 + ((c ^ (row & 7)) << 4);
                ldsm_x4(a[mtl][0], a[mtl][1], a[mtl][2], a[mtl][3], addr);
            }
            #pragma unroll
            for (int h = 0; h < 2; h++) {              // pairs of n-tiles
                uint32_t b0, b1, b2, b3;
                int nrow = wn * 32 + (2 * h + (q >> 1)) * 8 + g8;
                int c = ks * 2 + (q & 1);
                uint32_t addr = sB + nrow * 128 + ((c ^ (nrow & 7)) << 4);
                ldsm_x4(b0, b1, b2, b3, addr);
                uint32_t bl[2] = {b0, b1}, bh[2] = {b2, b3};
                mma_fp16(acc[0][2 * h],     a[0], bl);
                mma_fp16(acc[0][2 * h + 1], a[0], bh);
                mma_fp16(acc[1][2 * h],     a[1], bl);
                mma_fp16(acc[1][2 * h + 1], a[1], bh);
            }
        }
    };

    issue_stage(0, 0);
    issue_stage(1, BK);
    for (int it = 0; it < D / BK; it++) {              // 8 iterations
        asm volatile("cp.async.wait_group 1;" ::: "memory");
        __syncthreads();
        compute(it & 1);
        __syncthreads();
        if (it < D / BK - 2) issue_stage(it & 1, (it + 2) * BK);
        else asm volatile("cp.async.commit_group;" ::: "memory");  // keep group count
    }

    // epilogue: ys = dis[row] * y, stored fp16
    const int eg = lane >> 2, et = lane & 3;
    __half* yh = reinterpret_cast<__half*>(g_ys);
    #pragma unroll
    for (int mtl = 0; mtl < 2; mtl++) {
        const int rA = m0 + wm * 32 + mtl * 16 + eg;
        const float dA = g_dis[rA];
        const float dB = g_dis[rA + 8];
        #pragma unroll
        for (int ntl = 0; ntl < 4; ntl++) {
            const int cc = n0 + wn * 32 + ntl * 8 + et * 2;
            __half2 lo = __float22half2_rn(
                make_float2(dA * acc[mtl][ntl][0], dA * acc[mtl][ntl][1]));
            __half2 hi = __float22half2_rn(
                make_float2(dB * acc[mtl][ntl][2], dB * acc[mtl][ntl][3]));
            *reinterpret_cast<__half2*>(&yh[(size_t)rA * D + cc])       = lo;
            *reinterpret_cast<__half2*>(&yh[(size_t)(rA + 8) * D + cc]) = hi;
        }
    }
}

// =====================================================================
// Kernel 3: aggregate + bias + relu.  At the LTS chip-throughput cap
// (~12 TB/s L2 gather); two-level HADD2 accumulation.  Unchanged.
// =====================================================================
__device__ __forceinline__ void acc8f(float4& a0, float4& a1, uint4 v) {
    float2 p0 = __half22float2(*reinterpret_cast<__half2*>(&v.x));
    float2 p1 = __half22float2(*reinterpret_cast<__half2*>(&v.y));
    float2 p2 = __half22float2(*reinterpret_cast<__half2*>(&v.z));
    float2 p3 = __half22float2(*reinterpret_cast<__half2*>(&v.w));
    a0.x += p0.x; a0.y += p0.y; a0.z += p1.x; a0.w += p1.y;
    a1.x += p2.x; a1.y += p2.y; a1.z += p3.x; a1.w += p3.y;
}

__global__ __launch_bounds__(64) void aggregate_out_kernel(const float* __restrict__ bias,
                                                           float* __restrict__ out) {
    const int row = blockIdx.x;
    __shared__ int s_nbr[CAP];

    const int cnt = g_cnt[row];
    for (int e = threadIdx.x; e < cnt; e += 64) s_nbr[e] = g_csr[row * CAP + e];
    __syncthreads();

    const int c = threadIdx.x;                         // owns cols [8c, 8c+8)
    float4 a0 = make_float4(0.f, 0.f, 0.f, 0.f);
    float4 a1 = make_float4(0.f, 0.f, 0.f, 0.f);
    acc8f(a0, a1, g_ys[row * (D / 8) + c]);            // self term (fp32 path)

    int e = 0;
    for (; e + 8 <= cnt; e += 8) {
        __half2 h0 = __floats2half2_rn(0.f, 0.f);
        __half2 h1 = h0, h2 = h0, h3 = h0;
        #pragma unroll
        for (int u = 0; u < 8; u++) {
            uint4 v = g_ys[s_nbr[e + u] * (D / 8) + c];
            h0 = __hadd2(h0, *reinterpret_cast<__half2*>(&v.x));
            h1 = __hadd2(h1, *reinterpret_cast<__half2*>(&v.y));
            h2 = __hadd2(h2, *reinterpret_cast<__half2*>(&v.z));
            h3 = __hadd2(h3, *reinterpret_cast<__half2*>(&v.w));
        }
        float2 f0 = __half22float2(h0), f1 = __half22float2(h1);
        float2 f2 = __half22float2(h2), f3 = __half22float2(h3);
        a0.x += f0.x; a0.y += f0.y; a0.z += f1.x; a0.w += f1.y;
        a1.x += f2.x; a1.y += f2.y; a1.z += f3.x; a1.w += f3.y;
    }
    for (; e < cnt; e++) acc8f(a0, a1, g_ys[s_nbr[e] * (D / 8) + c]);

    const float di = g_dis[row];
    const float4 b0 = reinterpret_cast<const float4*>(bias)[2 * c];
    const float4 b1 = reinterpret_cast<const float4*>(bias)[2 * c + 1];
    float4 o0, o1;
    o0.x = fmaxf(di * a0.x + b0.x, 0.0f);
    o0.y = fmaxf(di * a0.y + b0.y, 0.0f);
    o0.z = fmaxf(di * a0.z + b0.z, 0.0f);
    o0.w = fmaxf(di * a0.w + b0.w, 0.0f);
    o1.x = fmaxf(di * a1.x + b1.x, 0.0f);
    o1.y = fmaxf(di * a1.y + b1.y, 0.0f);
    o1.z = fmaxf(di * a1.z + b1.z, 0.0f);
    o1.w = fmaxf(di * a1.w + b1.w, 0.0f);
    reinterpret_cast<float4*>(out)[row * (D / 4) + 2 * c]     = o0;
    reinterpret_cast<float4*>(out)[row * (D / 4) + 2 * c + 1] = o1;
}

// =====================================================================
extern "C" void kernel_launch(void* const* d_in, const int* in_sizes, int n_in,
                              void* d_out, int out_size) {
    const float *x = nullptr, *A = nullptr, *W = nullptr, *b = nullptr;
    for (int i = 0; i < n_in; i++) {
        switch (in_sizes[i]) {
            case XN:                       x = (const float*)d_in[i]; break;
            case 67108864 /* 8192^2 */:    A = (const float*)d_in[i]; break;
            case WN:                       W = (const float*)d_in[i]; break;
            case D:                        b = (const float*)d_in[i]; break;
        }
    }
    float* out = (float*)d_out;

    convert_kernel<<<(XN + WN) / 8 / 256, 256>>>(x, W);
    build_csr_kernel<<<N_NODES, 512>>>(A);             // writes g_cnt, g_dis
    gemm_kernel<<<(N_NODES / BM) * (D / BN), 256>>>();
    aggregate_out_kernel<<<N_NODES, 64>>>(b, out);
}

// round 17
// speedup vs baseline: 1.3574x; 1.0143x over previous
#include <cuda_runtime.h>
#include <cuda_fp16.h>
#include <cstdint>

#define N_NODES 8192
#define D       512
#define CAP     256
#define XN      (N_NODES * D)
#define WN      (D * D)
#define CONV_BLOCKS ((XN + WN) / 8 / 512)   // 1088 blocks of 512 thr, 8 floats each

// ---- scratch (device globals) ----
__device__ int    g_csr[N_NODES * CAP];
__device__ int    g_cnt[N_NODES];
__device__ float  g_dis[N_NODES];
__device__ uint4  g_ys[N_NODES * D / 8];   // ys = dis[m] * (x @ W^T)[m], fp16
__device__ __half g_xh[XN];                // fp16 copies of x and W (pre-converted)
__device__ __half g_wh[WN];

__device__ __forceinline__ uint32_t smem_u32(const void* p) {
    uint32_t a;
    asm("{ .reg .u64 t; cvta.to.shared.u64 t, %1; cvt.u32.u64 %0, t; }" : "=r"(a) : "l"(p));
    return a;
}
__device__ __forceinline__ uint32_t packh2(float a, float b) {
    __half2 h = __float22half2_rn(make_float2(a, b));
    return *reinterpret_cast<uint32_t*>(&h);
}
__device__ __forceinline__ void mma_fp16(float* c, const uint32_t* a, const uint32_t* b) {
    asm volatile(
        "mma.sync.aligned.m16n8k16.row.col.f32.f16.f16.f32 "
        "{%0,%1,%2,%3}, {%4,%5,%6,%7}, {%8,%9}, {%0,%1,%2,%3};\n"
        : "+f"(c[0]), "+f"(c[1]), "+f"(c[2]), "+f"(c[3])
        : "r"(a[0]), "r"(a[1]), "r"(a[2]), "r"(a[3]), "r"(b[0]), "r"(b[1]));
}
__device__ __forceinline__ void ldsm_x4(uint32_t& r0, uint32_t& r1, uint32_t& r2, uint32_t& r3,
                                        uint32_t addr) {
    asm volatile("ldmatrix.sync.aligned.m8n8.x4.shared.b16 {%0,%1,%2,%3}, [%4];"
                 : "=r"(r0), "=r"(r1), "=r"(r2), "=r"(r3) : "r"(addr));
}

// =====================================================================
// Kernel 1: CSR build + fp16 convert, one launch.
//   blocks [0, CONV_BLOCKS)          : convert x,W -> fp16 (30 MB, rides
//                                      in csr's spare LTS headroom)
//   blocks [CONV_BLOCKS, +N_NODES)   : scan one row of dense A -> CSR
// Both bodies: <=512 thr, ~26 regs, <=4B smem -> co-schedule cleanly.
// =====================================================================
__global__ __launch_bounds__(512) void csr_convert_kernel(const float* __restrict__ A,
                                                          const float* __restrict__ x,
                                                          const float* __restrict__ W) {
    const int bx = blockIdx.x;

    if (bx < CONV_BLOCKS) {
        // ---- convert branch: 8 floats / thread ----
        int idx = bx * 512 + threadIdx.x;
        const float4* s;
        uint4* d;
        if (idx < XN / 8) { s = reinterpret_cast<const float4*>(x); d = reinterpret_cast<uint4*>(g_xh); }
        else { s = reinterpret_cast<const float4*>(W); d = reinterpret_cast<uint4*>(g_wh); idx -= XN / 8; }
        float4 v0 = s[idx * 2], v1 = s[idx * 2 + 1];
        uint4 o;
        o.x = packh2(v0.x, v0.y); o.y = packh2(v0.z, v0.w);
        o.z = packh2(v1.x, v1.y); o.w = packh2(v1.z, v1.w);
        d[idx] = o;
        return;
    }

    // ---- CSR branch: one row of A per block ----
    const int row = bx - CONV_BLOCKS;
    __shared__ int s_cnt;
    if (threadIdx.x == 0) s_cnt = 0;
    __syncthreads();

    const float4* Arow = reinterpret_cast<const float4*>(A + (size_t)row * N_NODES);
    int* csr_row = g_csr + row * CAP;

    float4 f[4];
    #pragma unroll
    for (int i = 0; i < 4; i++)
        f[i] = __ldcs(&Arow[threadIdx.x + i * 512]);

    #pragma unroll
    for (int i = 0; i < 4; i++) {
        int base = (threadIdx.x + i * 512) * 4;
        if (f[i].x != 0.0f) { int s = atomicAdd(&s_cnt, 1); if (s < CAP) csr_row[s] = base;     }
        if (f[i].y != 0.0f) { int s = atomicAdd(&s_cnt, 1); if (s < CAP) csr_row[s] = base + 1; }
        if (f[i].z != 0.0f) { int s = atomicAdd(&s_cnt, 1); if (s < CAP) csr_row[s] = base + 2; }
        if (f[i].w != 0.0f) { int s = atomicAdd(&s_cnt, 1); if (s < CAP) csr_row[s] = base + 3; }
    }
    __syncthreads();
    if (threadIdx.x == 0) {
        int c = s_cnt;
        g_cnt[row] = (c < CAP) ? c : CAP;
        g_dis[row] = rsqrtf((float)(c + 1));           // A_tilde = A + I
    }
}

// =====================================================================
// Kernel 2: ys = dis * (xh @ Wh^T)  — cp.async + ldmatrix pipeline.
// At the legacy-mma.sync throughput ceiling (~13us); frozen.
// =====================================================================
#define BM 128
#define BN 64
#define BK 64
#define STAGE_BYTES 24576   // A 16KB + B 8KB

__global__ __launch_bounds__(256) void gemm_kernel() {
    __shared__ __align__(16) uint32_t smem[2 * STAGE_BYTES / 4];
    const uint32_t sbase = smem_u32(smem);
    const int tid = threadIdx.x;
    const int id = blockIdx.x;
    const int m0 = (id >> 3) * BM;
    const int n0 = (id & 7) * BN;

    const int wid = tid >> 5, lane = tid & 31;
    const int wm = wid & 3;                            // 4 warps in M
    const int wn = wid >> 2;                           // 2 warps in N
    const int g8 = lane & 7, q = lane >> 3;            // ldmatrix lane decomposition

    float acc[2][4][4];
    #pragma unroll
    for (int i = 0; i < 2; i++)
        #pragma unroll
        for (int j = 0; j < 4; j++)
            #pragma unroll
            for (int r = 0; r < 4; r++) acc[i][j][r] = 0.0f;

    auto issue_stage = [&](int stage, int k0) {
        const uint32_t sA = sbase + stage * STAGE_BYTES;
        const uint32_t sB = sA + 16384;
        #pragma unroll
        for (int i = 0; i < 4; i++) {                  // A: 1024 chunks of 16B
            int cid = tid + i * 256;
            int row = cid >> 3, c = cid & 7;
            uint32_t dst = sA + row * 128 + ((c ^ (row & 7)) << 4);
            asm volatile("cp.async.cg.shared.global [%0], [%1], 16;"
                         :: "r"(dst), "l"(&g_xh[(size_t)(m0 + row) * D + k0 + c * 8]) : "memory");
        }
        #pragma unroll
        for (int i = 0; i < 2; i++) {                  // B: 512 chunks
            int cid = tid + i * 256;
            int row = cid >> 3, c = cid & 7;
            uint32_t dst = sB + row * 128 + ((c ^ (row & 7)) << 4);
            asm volatile("cp.async.cg.shared.global [%0], [%1], 16;"
                         :: "r"(dst), "l"(&g_wh[(size_t)(n0 + row) * D + k0 + c * 8]) : "memory");
        }
        asm volatile("cp.async.commit_group;" ::: "memory");
    };

    auto compute = [&](int stage) {
        const uint32_t sA = sbase + stage * STAGE_BYTES;
        const uint32_t sB = sA + 16384;
        #pragma unroll
        for (int ks = 0; ks < 4; ks++) {               // 4 x k16 per BK=64
            uint32_t a[2][4];
            #pragma unroll
            for (int mtl = 0; mtl < 2; mtl++) {
                int row = wm * 32 + mtl * 16 + g8 + ((q & 1) << 3);
                int c = ks * 2 + (q >> 1);
                uint32_t addr = sA + row * 128 + ((c ^ (row & 7)) << 4);
                ldsm_x4(a[mtl][0], a[mtl][1], a[mtl][2], a[mtl][3], addr);
            }
            #pragma unroll
            for (int h = 0; h < 2; h++) {              // pairs of n-tiles
                uint32_t b0, b1, b2, b3;
                int nrow = wn * 32 + (2 * h + (q >> 1)) * 8 + g8;
                int c = ks * 2 + (q & 1);
                uint32_t addr = sB + nrow * 128 + ((c ^ (nrow & 7)) << 4);
                ldsm_x4(b0, b1, b2, b3, addr);
                uint32_t bl[2] = {b0, b1}, bh[2] = {b2, b3};
                mma_fp16(acc[0][2 * h],     a[0], bl);
                mma_fp16(acc[0][2 * h + 1], a[0], bh);
                mma_fp16(acc[1][2 * h],     a[1], bl);
                mma_fp16(acc[1][2 * h + 1], a[1], bh);
            }
        }
    };

    issue_stage(0, 0);
    issue_stage(1, BK);
    for (int it = 0; it < D / BK; it++) {              // 8 iterations
        asm volatile("cp.async.wait_group 1;" ::: "memory");
        __syncthreads();
        compute(it & 1);
        __syncthreads();
        if (it < D / BK - 2) issue_stage(it & 1, (it + 2) * BK);
        else asm volatile("cp.async.commit_group;" ::: "memory");  // keep group count
    }

    // epilogue: ys = dis[row] * y, stored fp16
    const int eg = lane >> 2, et = lane & 3;
    __half* yh = reinterpret_cast<__half*>(g_ys);
    #pragma unroll
    for (int mtl = 0; mtl < 2; mtl++) {
        const int rA = m0 + wm * 32 + mtl * 16 + eg;
        const float dA = g_dis[rA];
        const float dB = g_dis[rA + 8];
        #pragma unroll
        for (int ntl = 0; ntl < 4; ntl++) {
            const int cc = n0 + wn * 32 + ntl * 8 + et * 2;
            __half2 lo = __float22half2_rn(
                make_float2(dA * acc[mtl][ntl][0], dA * acc[mtl][ntl][1]));
            __half2 hi = __float22half2_rn(
                make_float2(dB * acc[mtl][ntl][2], dB * acc[mtl][ntl][3]));
            *reinterpret_cast<__half2*>(&yh[(size_t)rA * D + cc])       = lo;
            *reinterpret_cast<__half2*>(&yh[(size_t)(rA + 8) * D + cc]) = hi;
        }
    }
}

// =====================================================================
// Kernel 3: aggregate + bias + relu.  At the LTS chip-throughput cap
// (~12 TB/s L2 gather); two-level HADD2 accumulation.  Frozen.
// =====================================================================
__device__ __forceinline__ void acc8f(float4& a0, float4& a1, uint4 v) {
    float2 p0 = __half22float2(*reinterpret_cast<__half2*>(&v.x));
    float2 p1 = __half22float2(*reinterpret_cast<__half2*>(&v.y));
    float2 p2 = __half22float2(*reinterpret_cast<__half2*>(&v.z));
    float2 p3 = __half22float2(*reinterpret_cast<__half2*>(&v.w));
    a0.x += p0.x; a0.y += p0.y; a0.z += p1.x; a0.w += p1.y;
    a1.x += p2.x; a1.y += p2.y; a1.z += p3.x; a1.w += p3.y;
}

__global__ __launch_bounds__(64) void aggregate_out_kernel(const float* __restrict__ bias,
                                                           float* __restrict__ out) {
    const int row = blockIdx.x;
    __shared__ int s_nbr[CAP];

    const int cnt = g_cnt[row];
    for (int e = threadIdx.x; e < cnt; e += 64) s_nbr[e] = g_csr[row * CAP + e];
    __syncthreads();

    const int c = threadIdx.x;                         // owns cols [8c, 8c+8)
    float4 a0 = make_float4(0.f, 0.f, 0.f, 0.f);
    float4 a1 = make_float4(0.f, 0.f, 0.f, 0.f);
    acc8f(a0, a1, g_ys[row * (D / 8) + c]);            // self term (fp32 path)

    int e = 0;
    for (; e + 8 <= cnt; e += 8) {
        __half2 h0 = __floats2half2_rn(0.f, 0.f);
        __half2 h1 = h0, h2 = h0, h3 = h0;
        #pragma unroll
        for (int u = 0; u < 8; u++) {
            uint4 v = g_ys[s_nbr[e + u] * (D / 8) + c];
            h0 = __hadd2(h0, *reinterpret_cast<__half2*>(&v.x));
            h1 = __hadd2(h1, *reinterpret_cast<__half2*>(&v.y));
            h2 = __hadd2(h2, *reinterpret_cast<__half2*>(&v.z));
            h3 = __hadd2(h3, *reinterpret_cast<__half2*>(&v.w));
        }
        float2 f0 = __half22float2(h0), f1 = __half22float2(h1);
        float2 f2 = __half22float2(h2), f3 = __half22float2(h3);
        a0.x += f0.x; a0.y += f0.y; a0.z += f1.x; a0.w += f1.y;
        a1.x += f2.x; a1.y += f2.y; a1.z += f3.x; a1.w += f3.y;
    }
    for (; e < cnt; e++) acc8f(a0, a1, g_ys[s_nbr[e] * (D / 8) + c]);

    const float di = g_dis[row];
    const float4 b0 = reinterpret_cast<const float4*>(bias)[2 * c];
    const float4 b1 = reinterpret_cast<const float4*>(bias)[2 * c + 1];
    float4 o0, o1;
    o0.x = fmaxf(di * a0.x + b0.x, 0.0f);
    o0.y = fmaxf(di * a0.y + b0.y, 0.0f);
    o0.z = fmaxf(di * a0.z + b0.z, 0.0f);
    o0.w = fmaxf(di * a0.w + b0.w, 0.0f);
    o1.x = fmaxf(di * a1.x + b1.x, 0.0f);
    o1.y = fmaxf(di * a1.y + b1.y, 0.0f);
    o1.z = fmaxf(di * a1.z + b1.z, 0.0f);
    o1.w = fmaxf(di * a1.w + b1.w, 0.0f);
    reinterpret_cast<float4*>(out)[row * (D / 4) + 2 * c]     = o0;
    reinterpret_cast<float4*>(out)[row * (D / 4) + 2 * c + 1] = o1;
}

// =====================================================================
extern "C" void kernel_launch(void* const* d_in, const int* in_sizes, int n_in,
                              void* d_out, int out_size) {
    const float *x = nullptr, *A = nullptr, *W = nullptr, *b = nullptr;
    for (int i = 0; i < n_in; i++) {
        switch (in_sizes[i]) {
            case XN:                       x = (const float*)d_in[i]; break;
            case 67108864 /* 8192^2 */:    A = (const float*)d_in[i]; break;
            case WN:                       W = (const float*)d_in[i]; break;
            case D:                        b = (const float*)d_in[i]; break;
        }
    }
    float* out = (float*)d_out;

    csr_convert_kernel<<<CONV_BLOCKS + N_NODES, 512>>>(A, x, W);
    gemm_kernel<<<(N_NODES / BM) * (D / BN), 256>>>();
    aggregate_out_kernel<<<N_NODES, 64>>>(b, out);
}